// round 15
// baseline (speedup 1.0000x reference)
#include <cuda_runtime.h>
#include <math.h>

#define TSTEPS 64
#define BATCH  32
#define NH     512
#define NH2    1024
#define VOCAB  32000
#define RROWS  (TSTEPS*BATCH)   // 2048
#define SELEM  (BATCH*NH)       // 16384
#define BS_STRIDE 68            // padded dup-B row stride (floats), mult of 4
#define STG_SMEM ((NH*32 + 32*BS_STRIDE)*4)

typedef unsigned long long ull;

// packed fp32x2 FMA: 2 independent full-precision fp32 FMAs per instruction
#define FMA2(acc, a, b) \
    asm("fma.rn.f32x2 %0, %1, %2, %0;" : "+l"(acc) : "l"(a), "l"(b))
#define DUP2(d, s) \
    asm("mov.b64 %0, {%1, %1};" : "=l"(d) : "f"(s))

__device__ __forceinline__ float lo32(ull v) {
    float f; asm("{ .reg .f32 h; mov.b64 {%0, h}, %1; }" : "=f"(f) : "l"(v)); return f;
}
__device__ __forceinline__ float hi32(ull v) {
    float f; asm("{ .reg .f32 l; mov.b64 {l, %0}, %1; }" : "=f"(f) : "l"(v)); return f;
}

// ---------------------------------------------------------------------------
// Scratch (static device globals; no allocation anywhere)
// ---------------------------------------------------------------------------
__device__ __align__(16) float g_X[RROWS*NH];
__device__ __align__(16) float g_Xpre[RROWS*NH2];
__device__ __align__(16) float g_statesT[8][SELEM];   // transposed [d][b]
__device__ __align__(16) float g_hidT[RROWS*NH];      // [t][d][b]
__device__ __align__(16) float g_logits[(size_t)RROWS*VOCAB];

__device__ __forceinline__ float sigm(float x) { return 1.f / (1.f + expf(-x)); }

// ---------------------------------------------------------------------------
// Embedding gather
// ---------------------------------------------------------------------------
__global__ __launch_bounds__(128) void kEmbed(const int* __restrict__ ids,
                                              const float* __restrict__ emb) {
    int r = blockIdx.x;
    int row = ids[r];
    const float4* src = reinterpret_cast<const float4*>(emb + (size_t)row * NH);
    float4* dst = reinterpret_cast<float4*>(g_X + (size_t)r * NH);
    dst[threadIdx.x] = src[threadIdx.x];
}

// ---------------------------------------------------------------------------
// Xpre = g_X[2048,512] @ W0[0:512, 0:1024]  (64x64 tile, 4x4 micro)
// ---------------------------------------------------------------------------
__global__ __launch_bounds__(256) void kXpreGemm(const float* __restrict__ W0) {
    __shared__ __align__(16) float As[16][64];
    __shared__ __align__(16) float Bs[16][64];
    const int m0 = blockIdx.y * 64, n0 = blockIdx.x * 64;
    const int tid = threadIdx.x, tx = tid & 15, ty = tid >> 4;
    const int am = tid >> 2, ak4 = (tid & 3) * 4;
    const int bk = tid >> 4, bn4 = (tid & 15) * 4;
    float acc[4][4];
#pragma unroll
    for (int i = 0; i < 4; i++)
#pragma unroll
        for (int j = 0; j < 4; j++) acc[i][j] = 0.f;
    for (int k0 = 0; k0 < NH; k0 += 16) {
        float4 av = *reinterpret_cast<const float4*>(g_X + (size_t)(m0+am)*NH + k0 + ak4);
        As[ak4+0][am] = av.x; As[ak4+1][am] = av.y; As[ak4+2][am] = av.z; As[ak4+3][am] = av.w;
        *reinterpret_cast<float4*>(&Bs[bk][bn4]) =
            *reinterpret_cast<const float4*>(W0 + (size_t)(k0+bk)*NH2 + n0 + bn4);
        __syncthreads();
#pragma unroll
        for (int kk = 0; kk < 16; kk++) {
            float4 a = *reinterpret_cast<float4*>(&As[kk][ty*4]);
            float4 b = *reinterpret_cast<float4*>(&Bs[kk][tx*4]);
            float aa[4] = {a.x,a.y,a.z,a.w}, bb[4] = {b.x,b.y,b.z,b.w};
#pragma unroll
            for (int i = 0; i < 4; i++)
#pragma unroll
                for (int j = 0; j < 4; j++) acc[i][j] += aa[i]*bb[j];
        }
        __syncthreads();
    }
#pragma unroll
    for (int i = 0; i < 4; i++) {
        float4 st = make_float4(acc[i][0], acc[i][1], acc[i][2], acc[i][3]);
        *reinterpret_cast<float4*>(g_Xpre + (size_t)(m0+ty*4+i)*NH2 + n0 + tx*4) = st;
    }
}

// ---------------------------------------------------------------------------
// Unified stage kernel (f32x2 core).
//   i == -1 : node0.  i >= 0 : edge stage, j = i+1+blockIdx.y.
// Tile: 32 batch x 16 (c,h) column pairs. 128 threads, full-K A in smem.
// Bs holds duplicated weight pairs: row kk has c-pairs [0..32), h-pairs [32..64).
// ---------------------------------------------------------------------------
__global__ __launch_bounds__(128, 2) void kStage(const float* __restrict__ Wbase,
                                                 const float* __restrict__ h0in,
                                                 int i, int t) {
    extern __shared__ float smem[];
    float* As = smem;               // [512][32]  ([k][b])
    float* Bs = smem + NH * 32;     // [32][BS_STRIDE] duplicated pairs
    const int tid = threadIdx.x;
    const int d0 = blockIdx.x << 4;

    // ---- prologue: stage A into As[k][b]
    if (i >= 0) {
        const float inv = (i == 0) ? 1.f : 1.f / (float)i;
        const float4* S4 = reinterpret_cast<const float4*>(g_statesT[i]);
        float4* A4 = reinterpret_cast<float4*>(As);
#pragma unroll 4
        for (int w = 0; w < 32; w++) {
            float4 v = S4[w*128 + tid];
            v.x *= inv; v.y *= inv; v.z *= inv; v.w *= inv;
            A4[w*128 + tid] = v;
        }
    } else if (t > 0) {
        float4* A4 = reinterpret_cast<float4*>(As);
        float4* H4 = reinterpret_cast<float4*>(g_hidT + (size_t)(t-1)*SELEM);
        const bool wr = (blockIdx.x == 0);
#pragma unroll 2
        for (int w = 0; w < 32; w++) {
            float4 a = make_float4(0.f, 0.f, 0.f, 0.f);
#pragma unroll
            for (int jj = 1; jj < 8; jj++) {
                float4 v = reinterpret_cast<const float4*>(g_statesT[jj])[w*128 + tid];
                float wg = 1.f / (float)jj;
                a.x += v.x*wg; a.y += v.y*wg; a.z += v.z*wg; a.w += v.w*wg;
            }
            const float c7 = 1.f / 7.f;
            a.x *= c7; a.y *= c7; a.z *= c7; a.w *= c7;
            A4[w*128 + tid] = a;
            if (wr) H4[w*128 + tid] = a;
        }
    } else {
        // t == 0: transpose h0in [b][d] -> As[d][b]
        const int b = tid & 31, kg = (tid >> 5) << 3;
        for (int kb = 0; kb < NH; kb += 32) {
            const int k = kb + kg;
            float4 p0 = *reinterpret_cast<const float4*>(h0in + b*NH + k);
            float4 p1 = *reinterpret_cast<const float4*>(h0in + b*NH + k + 4);
            As[(k+0)*32+b]=p0.x; As[(k+1)*32+b]=p0.y; As[(k+2)*32+b]=p0.z; As[(k+3)*32+b]=p0.w;
            As[(k+4)*32+b]=p1.x; As[(k+5)*32+b]=p1.y; As[(k+6)*32+b]=p1.z; As[(k+7)*32+b]=p1.w;
        }
    }

    int j = 0;
    const float* W;
    if (i < 0) { W = Wbase; }
    else { j = i + 1 + blockIdx.y; W = Wbase + ((size_t)(i*8 + j) << 19); }

    __syncthreads();

    const int tx = tid & 15, ty = tid >> 4;   // tx: pair col; ty: batch group
    const int b0 = ty << 2;
    const int r  = tid >> 2, f4 = (tid & 3) << 2;
    ull c01 = 0ull, c23 = 0ull, h01 = 0ull, h23 = 0ull;

    // prefetch first B chunk (rows r, cols d0+f4..+3 / NH+d0+f4..+3)
    const float* wr0 = W + (size_t)r * NH2 + d0;
    float4 pc = __ldg(reinterpret_cast<const float4*>(wr0 + f4));
    float4 ph = __ldg(reinterpret_cast<const float4*>(wr0 + NH + f4));

    for (int k0 = 0; k0 < NH; k0 += 32) {
        // store duplicated pairs
        *reinterpret_cast<float4*>(Bs + r*BS_STRIDE + 2*f4)          = make_float4(pc.x,pc.x,pc.y,pc.y);
        *reinterpret_cast<float4*>(Bs + r*BS_STRIDE + 2*f4 + 4)      = make_float4(pc.z,pc.z,pc.w,pc.w);
        *reinterpret_cast<float4*>(Bs + r*BS_STRIDE + 32 + 2*f4)     = make_float4(ph.x,ph.x,ph.y,ph.y);
        *reinterpret_cast<float4*>(Bs + r*BS_STRIDE + 32 + 2*f4 + 4) = make_float4(ph.z,ph.z,ph.w,ph.w);
        __syncthreads();
        if (k0 + 32 < NH) {
            const float* wrn = W + (size_t)(k0 + 32 + r) * NH2 + d0;
            pc = __ldg(reinterpret_cast<const float4*>(wrn + f4));
            ph = __ldg(reinterpret_cast<const float4*>(wrn + NH + f4));
        }
#pragma unroll 8
        for (int kk = 0; kk < 32; kk++) {
            ull a01 = *reinterpret_cast<const ull*>(As + (k0+kk)*32 + b0);
            ull a23 = *reinterpret_cast<const ull*>(As + (k0+kk)*32 + b0 + 2);
            ull bc  = *reinterpret_cast<const ull*>(Bs + kk*BS_STRIDE + 2*tx);
            ull bh  = *reinterpret_cast<const ull*>(Bs + kk*BS_STRIDE + 32 + 2*tx);
            FMA2(c01, a01, bc); FMA2(c23, a23, bc);
            FMA2(h01, a01, bh); FMA2(h23, a23, bh);
        }
        __syncthreads();
    }

    float cA[4] = {lo32(c01), hi32(c01), lo32(c23), hi32(c23)};
    float hA[4] = {lo32(h01), hi32(h01), lo32(h23), hi32(h23)};
    const int d = d0 + tx;
    if (i < 0) {
        const float* xp = g_Xpre + ((size_t)t * BATCH) * NH2;
        float s[4];
#pragma unroll
        for (int q = 0; q < 4; q++) {
            const int b = b0 + q;
            float cc = cA[q] + __ldg(xp + b*NH2 + d);
            float hh = hA[q] + __ldg(xp + b*NH2 + NH + d);
            float hp = As[d*32 + b];
            s[q] = hp + sigm(cc) * (tanhf(hh) - hp);
        }
        *reinterpret_cast<float4*>(g_statesT[0] + d*32 + b0) =
            make_float4(s[0], s[1], s[2], s[3]);
    } else {
        float s[4];
#pragma unroll
        for (int q = 0; q < 4; q++) {
            const int b = b0 + q;
            float sp = As[d*32 + b];         // already scaled by inv
            float hh = hA[q];
            float act;
            if (j == 1 || j == 4)      act = tanhf(hh);
            else if (j == 2 || j == 5) act = fmaxf(hh, 0.f);
            else if (j == 3 || j == 6) act = sigm(hh);
            else                       act = hh;    // j == 7 identity
            s[q] = sp + sigm(cA[q]) * (act - sp);
        }
        float4* dst = reinterpret_cast<float4*>(g_statesT[j] + d*32 + b0);
        if (i == 0) *dst = make_float4(s[0], s[1], s[2], s[3]);
        else {
            float4 o = *dst;
            *dst = make_float4(o.x+s[0], o.y+s[1], o.z+s[2], o.w+s[3]);
        }
    }
}

// ---------------------------------------------------------------------------
// Final avg: write g_hidT[63] and last_h output (row-major [b][d])
// ---------------------------------------------------------------------------
__global__ __launch_bounds__(256) void kAvgFinal(float* __restrict__ lastOut) {
    int idx = blockIdx.x * 256 + threadIdx.x;   // = d*32 + b
    float s = 0.f;
#pragma unroll
    for (int jj = 1; jj < 8; jj++) s += g_statesT[jj][idx] * (1.f / (float)jj);
    s *= (1.f / 7.f);
    g_hidT[(size_t)(TSTEPS-1) * SELEM + idx] = s;
    int d = idx >> 5, b = idx & 31;
    lastOut[b * NH + d] = s;
}

// ---------------------------------------------------------------------------
// Decoder: logits[r,v] = hid[r,:] . emb[v,:] + bias[v]  (128x128, 8x8 micro,
// f32x2 packed core: acc pairs along rows, B duplicated on the fly)
// ---------------------------------------------------------------------------
__global__ __launch_bounds__(256) void kDec2(const float* __restrict__ emb,
                                             const float* __restrict__ bias) {
    __shared__ __align__(16) float As[16][132];
    __shared__ __align__(16) float Bs[16][132];
    const int m0 = blockIdx.y << 7, n0 = blockIdx.x << 7;
    const int tRow0 = m0 >> 5;                 // 4 consecutive t indices
    const int tid = threadIdx.x;
    const int tx = tid & 15, ty = tid >> 4;
    const int lr = tid >> 1, lk = (tid & 1) << 3;
    ull acc2[4][8];
#pragma unroll
    for (int i = 0; i < 4; i++)
#pragma unroll
        for (int j = 0; j < 8; j++) acc2[i][j] = 0ull;
    const float* Bp = emb + (size_t)(n0 + lr) * NH + lk;

    for (int k0 = 0; k0 < NH; k0 += 16) {
        // A: 512 float4 slots from g_hidT [t][k][b]
        {
            int s2 = tid;
#pragma unroll
            for (int rep = 0; rep < 2; rep++) {
                int tg = s2 >> 7, kk = (s2 >> 3) & 15, b4 = (s2 & 7) << 2;
                float4 v = *reinterpret_cast<const float4*>(
                    g_hidT + (size_t)(tRow0 + tg)*SELEM + (k0+kk)*32 + b4);
                *reinterpret_cast<float4*>(&As[kk][tg*32 + b4]) = v;
                s2 += 256;
            }
        }
        float4 b0v = __ldg(reinterpret_cast<const float4*>(Bp + k0));
        float4 b1v = __ldg(reinterpret_cast<const float4*>(Bp + k0 + 4));
        Bs[lk+0][lr]=b0v.x; Bs[lk+1][lr]=b0v.y; Bs[lk+2][lr]=b0v.z; Bs[lk+3][lr]=b0v.w;
        Bs[lk+4][lr]=b1v.x; Bs[lk+5][lr]=b1v.y; Bs[lk+6][lr]=b1v.z; Bs[lk+7][lr]=b1v.w;
        __syncthreads();
#pragma unroll
        for (int kk = 0; kk < 16; kk++) {
            ull a2[4];
            a2[0] = *reinterpret_cast<const ull*>(&As[kk][(ty<<3) + 0]);
            a2[1] = *reinterpret_cast<const ull*>(&As[kk][(ty<<3) + 2]);
            a2[2] = *reinterpret_cast<const ull*>(&As[kk][(ty<<3) + 4]);
            a2[3] = *reinterpret_cast<const ull*>(&As[kk][(ty<<3) + 6]);
            float4 u0 = *reinterpret_cast<const float4*>(&Bs[kk][tx<<3]);
            float4 u1 = *reinterpret_cast<const float4*>(&Bs[kk][(tx<<3)+4]);
            ull b2[8];
            DUP2(b2[0], u0.x); DUP2(b2[1], u0.y); DUP2(b2[2], u0.z); DUP2(b2[3], u0.w);
            DUP2(b2[4], u1.x); DUP2(b2[5], u1.y); DUP2(b2[6], u1.z); DUP2(b2[7], u1.w);
#pragma unroll
            for (int ip = 0; ip < 4; ip++)
#pragma unroll
                for (int j = 0; j < 8; j++)
                    FMA2(acc2[ip][j], a2[ip], b2[j]);
        }
        __syncthreads();
    }
    float4 bz0 = __ldg(reinterpret_cast<const float4*>(bias + n0 + (tx<<3)));
    float4 bz1 = __ldg(reinterpret_cast<const float4*>(bias + n0 + (tx<<3) + 4));
    float bb[8] = {bz0.x,bz0.y,bz0.z,bz0.w,bz1.x,bz1.y,bz1.z,bz1.w};
#pragma unroll
    for (int ip = 0; ip < 4; ip++) {
        float rl[8], rh[8];
#pragma unroll
        for (int j = 0; j < 8; j++) {
            rl[j] = lo32(acc2[ip][j]) + bb[j];
            rh[j] = hi32(acc2[ip][j]) + bb[j];
        }
        int rowL = m0 + (ty<<3) + (ip<<1);
        float* oL = g_logits + (size_t)rowL * VOCAB + n0 + (tx<<3);
        float* oH = oL + VOCAB;
        *reinterpret_cast<float4*>(oL)     = make_float4(rl[0], rl[1], rl[2], rl[3]);
        *reinterpret_cast<float4*>(oL + 4) = make_float4(rl[4], rl[5], rl[6], rl[7]);
        *reinterpret_cast<float4*>(oH)     = make_float4(rh[0], rh[1], rh[2], rh[3]);
        *reinterpret_cast<float4*>(oH + 4) = make_float4(rh[4], rh[5], rh[6], rh[7]);
    }
}

// ---------------------------------------------------------------------------
// Online log-softmax per row
// ---------------------------------------------------------------------------
__global__ __launch_bounds__(256) void kSoftmax(float* __restrict__ out) {
    const int r = blockIdx.x;
    const float* __restrict__ row = g_logits + (size_t)r * VOCAB;
    float m = -INFINITY, s = 0.f;
    for (int v = threadIdx.x; v < VOCAB; v += 256) {
        float x = row[v];
        if (x > m) { s = s * expf(m - x) + 1.f; m = x; }
        else       { s += expf(x - m); }
    }
    __shared__ float sm[256], ss[256];
    sm[threadIdx.x] = m; ss[threadIdx.x] = s;
    __syncthreads();
    for (int st = 128; st > 0; st >>= 1) {
        if (threadIdx.x < st) {
            float m2 = sm[threadIdx.x + st], s2 = ss[threadIdx.x + st];
            float m1 = sm[threadIdx.x],      s1 = ss[threadIdx.x];
            float M = fmaxf(m1, m2);
            sm[threadIdx.x] = M;
            ss[threadIdx.x] = s1 * expf(m1 - M) + s2 * expf(m2 - M);
        }
        __syncthreads();
    }
    const float lse = sm[0] + logf(ss[0]);
    float* __restrict__ orow = out + (size_t)r * VOCAB;
    for (int v = threadIdx.x; v < VOCAB; v += 256)
        orow[v] = row[v] - lse;
}

// ---------------------------------------------------------------------------
// Launch
// ---------------------------------------------------------------------------
extern "C" void kernel_launch(void* const* d_in, const int* in_sizes, int n_in,
                              void* d_out, int out_size) {
    const int*   ids  = (const int*)  d_in[0];   // [64,32]
    const float* h0   = (const float*)d_in[1];   // [1,32,512]
    const float* emb  = (const float*)d_in[2];   // [32000,512]
    const float* W0   = (const float*)d_in[3];   // [1024,1024]
    const float* Ws   = (const float*)d_in[4];   // [8,8,512,1024]
    const float* bias = (const float*)d_in[5];   // [32000]
    float* out = (float*)d_out;                  // [64,32,32000] ++ [1,32,512]

    cudaFuncSetAttribute(kStage, cudaFuncAttributeMaxDynamicSharedMemorySize, STG_SMEM);

    kEmbed<<<RROWS, 128>>>(ids, emb);
    kXpreGemm<<<dim3(NH2/64, RROWS/64), 256>>>(W0);

    const float* W0h = W0 + (size_t)NH * NH2;
    for (int t = 0; t < TSTEPS; t++) {
        kStage<<<dim3(32, 1), 128, STG_SMEM>>>(W0h, h0, -1, t);
        for (int i = 0; i < 7; i++)
            kStage<<<dim3(32, 7 - i), 128, STG_SMEM>>>(Ws, nullptr, i, t);
    }
    kAvgFinal<<<64, 256>>>(out + (size_t)RROWS * VOCAB);

    kDec2<<<dim3(VOCAB/128, RROWS/128), 256>>>(emb, bias);
    kSoftmax<<<RROWS, 256>>>(out);
}

// round 16
// speedup vs baseline: 1.2469x; 1.2469x over previous
#include <cuda_runtime.h>
#include <math.h>

#define TSTEPS 64
#define BATCH  32
#define NH     512
#define NH2    1024
#define VOCAB  32000
#define RROWS  (TSTEPS*BATCH)   // 2048
#define SELEM  (BATCH*NH)       // 16384
#define STG_SMEM ((NH*32 + 32*32)*4)   // 69632 bytes

// ---------------------------------------------------------------------------
// Scratch (static device globals; no allocation anywhere)
// ---------------------------------------------------------------------------
__device__ __align__(16) float g_X[RROWS*NH];
__device__ __align__(16) float g_Xpre[RROWS*NH2];
__device__ __align__(16) float g_statesT[8][SELEM];   // transposed [d][b]
__device__ __align__(16) float g_hidT[RROWS*NH];      // [t][d][b]
__device__ __align__(16) float g_logits[(size_t)RROWS*VOCAB];

__device__ __forceinline__ float sigm(float x) { return 1.f / (1.f + expf(-x)); }

__device__ __forceinline__ unsigned f2tf(float f) {
    unsigned u; asm("cvt.rna.tf32.f32 %0, %1;" : "=r"(u) : "f"(f)); return u;
}

// ---------------------------------------------------------------------------
// Embedding gather
// ---------------------------------------------------------------------------
__global__ __launch_bounds__(128) void kEmbed(const int* __restrict__ ids,
                                              const float* __restrict__ emb) {
    int r = blockIdx.x;
    int row = ids[r];
    const float4* src = reinterpret_cast<const float4*>(emb + (size_t)row * NH);
    float4* dst = reinterpret_cast<float4*>(g_X + (size_t)r * NH);
    dst[threadIdx.x] = src[threadIdx.x];
}

// ---------------------------------------------------------------------------
// Xpre = g_X[2048,512] @ W0[0:512, 0:1024]  (64x64 tile, 4x4 micro)
// ---------------------------------------------------------------------------
__global__ __launch_bounds__(256) void kXpreGemm(const float* __restrict__ W0) {
    __shared__ __align__(16) float As[16][64];
    __shared__ __align__(16) float Bs[16][64];
    const int m0 = blockIdx.y * 64, n0 = blockIdx.x * 64;
    const int tid = threadIdx.x, tx = tid & 15, ty = tid >> 4;
    const int am = tid >> 2, ak4 = (tid & 3) * 4;
    const int bk = tid >> 4, bn4 = (tid & 15) * 4;
    float acc[4][4];
#pragma unroll
    for (int i = 0; i < 4; i++)
#pragma unroll
        for (int j = 0; j < 4; j++) acc[i][j] = 0.f;
    for (int k0 = 0; k0 < NH; k0 += 16) {
        float4 av = *reinterpret_cast<const float4*>(g_X + (size_t)(m0+am)*NH + k0 + ak4);
        As[ak4+0][am] = av.x; As[ak4+1][am] = av.y; As[ak4+2][am] = av.z; As[ak4+3][am] = av.w;
        *reinterpret_cast<float4*>(&Bs[bk][bn4]) =
            *reinterpret_cast<const float4*>(W0 + (size_t)(k0+bk)*NH2 + n0 + bn4);
        __syncthreads();
#pragma unroll
        for (int kk = 0; kk < 16; kk++) {
            float4 a = *reinterpret_cast<float4*>(&As[kk][ty*4]);
            float4 b = *reinterpret_cast<float4*>(&Bs[kk][tx*4]);
            float aa[4] = {a.x,a.y,a.z,a.w}, bb[4] = {b.x,b.y,b.z,b.w};
#pragma unroll
            for (int i = 0; i < 4; i++)
#pragma unroll
                for (int j = 0; j < 4; j++) acc[i][j] += aa[i]*bb[j];
        }
        __syncthreads();
    }
#pragma unroll
    for (int i = 0; i < 4; i++) {
        float4 st = make_float4(acc[i][0], acc[i][1], acc[i][2], acc[i][3]);
        *reinterpret_cast<float4*>(g_Xpre + (size_t)(m0+ty*4+i)*NH2 + n0 + tx*4) = st;
    }
}

// ---------------------------------------------------------------------------
// Unified stage kernel (scalar FFMA core — proven fastest).
//   i == -1 : node0.  i >= 0 : edge stage, j = i+1+blockIdx.y.
// Tile: 32 batch x 16 (c,h) column pairs. 128 threads, full-K A in smem.
// ---------------------------------------------------------------------------
__global__ __launch_bounds__(128, 2) void kStage(const float* __restrict__ Wbase,
                                                 const float* __restrict__ h0in,
                                                 int i, int t) {
    extern __shared__ float smem[];
    float* As = smem;               // [512][32]  ([k][b])
    float* Bs = smem + NH * 32;     // [32][32]   (c cols 0..15 | h cols 16..31)
    const int tid = threadIdx.x;
    const int d0 = blockIdx.x << 4;

    // ---- prologue: stage A into As[k][b]
    if (i >= 0) {
        const float inv = (i == 0) ? 1.f : 1.f / (float)i;
        const float4* S4 = reinterpret_cast<const float4*>(g_statesT[i]);
        float4* A4 = reinterpret_cast<float4*>(As);
#pragma unroll 4
        for (int w = 0; w < 32; w++) {
            float4 v = S4[w*128 + tid];
            v.x *= inv; v.y *= inv; v.z *= inv; v.w *= inv;
            A4[w*128 + tid] = v;
        }
    } else if (t > 0) {
        float4* A4 = reinterpret_cast<float4*>(As);
        float4* H4 = reinterpret_cast<float4*>(g_hidT + (size_t)(t-1)*SELEM);
        const bool wr = (blockIdx.x == 0);
#pragma unroll 2
        for (int w = 0; w < 32; w++) {
            float4 a = make_float4(0.f, 0.f, 0.f, 0.f);
#pragma unroll
            for (int jj = 1; jj < 8; jj++) {
                float4 v = reinterpret_cast<const float4*>(g_statesT[jj])[w*128 + tid];
                float wg = 1.f / (float)jj;
                a.x += v.x*wg; a.y += v.y*wg; a.z += v.z*wg; a.w += v.w*wg;
            }
            const float c7 = 1.f / 7.f;
            a.x *= c7; a.y *= c7; a.z *= c7; a.w *= c7;
            A4[w*128 + tid] = a;
            if (wr) H4[w*128 + tid] = a;
        }
    } else {
        // t == 0: transpose h0in [b][d] -> As[d][b]
        const int b = tid & 31, kg = (tid >> 5) << 3;
        for (int kb = 0; kb < NH; kb += 32) {
            const int k = kb + kg;
            float4 p0 = *reinterpret_cast<const float4*>(h0in + b*NH + k);
            float4 p1 = *reinterpret_cast<const float4*>(h0in + b*NH + k + 4);
            As[(k+0)*32+b]=p0.x; As[(k+1)*32+b]=p0.y; As[(k+2)*32+b]=p0.z; As[(k+3)*32+b]=p0.w;
            As[(k+4)*32+b]=p1.x; As[(k+5)*32+b]=p1.y; As[(k+6)*32+b]=p1.z; As[(k+7)*32+b]=p1.w;
        }
    }

    int j = 0;
    const float* W;
    if (i < 0) { W = Wbase; }
    else { j = i + 1 + blockIdx.y; W = Wbase + ((size_t)(i*8 + j) << 19); }

    __syncthreads();

    const int tx = tid & 15, ty = tid >> 4;   // tx: pair col; ty: batch group
    const int b0 = ty << 2;
    const int r  = tid >> 2, f4 = (tid & 3) << 2;
    float cA[4] = {0,0,0,0}, hA[4] = {0,0,0,0};

    // prefetch first B chunk
    const float* wr0 = W + (size_t)r * NH2 + d0;
    float4 pc = __ldg(reinterpret_cast<const float4*>(wr0 + f4));
    float4 ph = __ldg(reinterpret_cast<const float4*>(wr0 + NH + f4));

    for (int k0 = 0; k0 < NH; k0 += 32) {
        *reinterpret_cast<float4*>(Bs + r*32 + f4)      = pc;
        *reinterpret_cast<float4*>(Bs + r*32 + 16 + f4) = ph;
        __syncthreads();
        if (k0 + 32 < NH) {
            const float* wrn = W + (size_t)(k0 + 32 + r) * NH2 + d0;
            pc = __ldg(reinterpret_cast<const float4*>(wrn + f4));
            ph = __ldg(reinterpret_cast<const float4*>(wrn + NH + f4));
        }
#pragma unroll 8
        for (int kk = 0; kk < 32; kk++) {
            float4 a = *reinterpret_cast<const float4*>(As + (k0+kk)*32 + b0);
            float bc = Bs[kk*32 + tx];
            float bh = Bs[kk*32 + 16 + tx];
            cA[0] = fmaf(a.x, bc, cA[0]); hA[0] = fmaf(a.x, bh, hA[0]);
            cA[1] = fmaf(a.y, bc, cA[1]); hA[1] = fmaf(a.y, bh, hA[1]);
            cA[2] = fmaf(a.z, bc, cA[2]); hA[2] = fmaf(a.z, bh, hA[2]);
            cA[3] = fmaf(a.w, bc, cA[3]); hA[3] = fmaf(a.w, bh, hA[3]);
        }
        __syncthreads();
    }

    const int d = d0 + tx;
    if (i < 0) {
        const float* xp = g_Xpre + ((size_t)t * BATCH) * NH2;
        float s[4];
#pragma unroll
        for (int q = 0; q < 4; q++) {
            const int b = b0 + q;
            float cc = cA[q] + __ldg(xp + b*NH2 + d);
            float hh = hA[q] + __ldg(xp + b*NH2 + NH + d);
            float hp = As[d*32 + b];
            s[q] = hp + sigm(cc) * (tanhf(hh) - hp);
        }
        *reinterpret_cast<float4*>(g_statesT[0] + d*32 + b0) =
            make_float4(s[0], s[1], s[2], s[3]);
    } else {
        float s[4];
#pragma unroll
        for (int q = 0; q < 4; q++) {
            const int b = b0 + q;
            float sp = As[d*32 + b];         // already scaled by inv
            float hh = hA[q];
            float act;
            if (j == 1 || j == 4)      act = tanhf(hh);
            else if (j == 2 || j == 5) act = fmaxf(hh, 0.f);
            else if (j == 3 || j == 6) act = sigm(hh);
            else                       act = hh;    // j == 7 identity
            s[q] = sp + sigm(cA[q]) * (act - sp);
        }
        float4* dst = reinterpret_cast<float4*>(g_statesT[j] + d*32 + b0);
        if (i == 0) *dst = make_float4(s[0], s[1], s[2], s[3]);
        else {
            float4 o = *dst;
            *dst = make_float4(o.x+s[0], o.y+s[1], o.z+s[2], o.w+s[3]);
        }
    }
}

// ---------------------------------------------------------------------------
// Final avg: write g_hidT[63] and last_h output (row-major [b][d])
// ---------------------------------------------------------------------------
__global__ __launch_bounds__(256) void kAvgFinal(float* __restrict__ lastOut) {
    int idx = blockIdx.x * 256 + threadIdx.x;   // = d*32 + b
    float s = 0.f;
#pragma unroll
    for (int jj = 1; jj < 8; jj++) s += g_statesT[jj][idx] * (1.f / (float)jj);
    s *= (1.f / 7.f);
    g_hidT[(size_t)(TSTEPS-1) * SELEM + idx] = s;
    int d = idx >> 5, b = idx & 31;
    lastOut[b * NH + d] = s;
}

// ---------------------------------------------------------------------------
// Decoder via tensor cores: mma.sync.m16n8k8 tf32.
// logits[r,v] = hid[r,:] . emb[v,:] + bias[v]
// Block: 256 thr (8 warps), tile 128(M) x 64(N) x 32(K).
// Warps: warpM=warp>>1 (0..3), warpN=warp&1 (0..1); warp tile 32x32.
// A from g_hidT [t][k][b] (m = t*32+b). smem stride 36 -> conflict-free frags.
// ---------------------------------------------------------------------------
__global__ __launch_bounds__(256) void kDecMMA(const float* __restrict__ emb,
                                               const float* __restrict__ bias) {
    __shared__ float As[128][36];   // [m][k] tf32 bits, 18KB
    __shared__ float Bs[64][36];    // [n][k] tf32 bits,  9KB
    const int n0 = blockIdx.x << 6, m0 = blockIdx.y << 7;
    const int tRow0 = m0 >> 5;
    const int tid = threadIdx.x;
    const int warp = tid >> 5, lane = tid & 31;
    const int warpM = warp >> 1, warpN = warp & 1;
    const int r = lane >> 2, c = lane & 3;

    float acc[2][4][4];
#pragma unroll
    for (int mt = 0; mt < 2; mt++)
#pragma unroll
        for (int nt = 0; nt < 4; nt++)
#pragma unroll
            for (int q = 0; q < 4; q++) acc[mt][nt][q] = 0.f;

    for (int k0 = 0; k0 < NH; k0 += 32) {
        // ---- load A tile: 128 x 32 (4096 elems, 16/thread as 4 float4 along b)
#pragma unroll
        for (int rep = 0; rep < 4; rep++) {
            int slot = tid + rep*256;           // 0..1023
            int tg = slot >> 8;                  // 0..3
            int rem = slot & 255;
            int kk = rem >> 3;                   // 0..31
            int b4 = (rem & 7) << 2;             // 0,4,..,28
            float4 v = *reinterpret_cast<const float4*>(
                g_hidT + (size_t)(tRow0 + tg)*SELEM + (size_t)(k0+kk)*32 + b4);
            int m = tg*32 + b4;
            As[m+0][kk] = __uint_as_float(f2tf(v.x));
            As[m+1][kk] = __uint_as_float(f2tf(v.y));
            As[m+2][kk] = __uint_as_float(f2tf(v.z));
            As[m+3][kk] = __uint_as_float(f2tf(v.w));
        }
        // ---- load B tile: 64 x 32 (2048 elems, 8/thread as 2 float4 along k)
#pragma unroll
        for (int rep = 0; rep < 2; rep++) {
            int slot = tid + rep*256;           // 0..511
            int n = slot >> 3;                   // 0..63
            int k4 = (slot & 7) << 2;            // 0,4,..,28
            float4 v = __ldg(reinterpret_cast<const float4*>(
                emb + (size_t)(n0+n)*NH + k0 + k4));
            float4 w;
            w.x = __uint_as_float(f2tf(v.x));
            w.y = __uint_as_float(f2tf(v.y));
            w.z = __uint_as_float(f2tf(v.z));
            w.w = __uint_as_float(f2tf(v.w));
            *reinterpret_cast<float4*>(&Bs[n][k4]) = w;
        }
        __syncthreads();

#pragma unroll
        for (int kb = 0; kb < 32; kb += 8) {
            unsigned a[2][4], b[4][2];
#pragma unroll
            for (int mt = 0; mt < 2; mt++) {
                int m = warpM*32 + mt*16 + r;
                a[mt][0] = __float_as_uint(As[m  ][kb + c]);
                a[mt][1] = __float_as_uint(As[m+8][kb + c]);
                a[mt][2] = __float_as_uint(As[m  ][kb + c + 4]);
                a[mt][3] = __float_as_uint(As[m+8][kb + c + 4]);
            }
#pragma unroll
            for (int nt = 0; nt < 4; nt++) {
                int n = warpN*32 + nt*8 + r;
                b[nt][0] = __float_as_uint(Bs[n][kb + c]);
                b[nt][1] = __float_as_uint(Bs[n][kb + c + 4]);
            }
#pragma unroll
            for (int mt = 0; mt < 2; mt++)
#pragma unroll
                for (int nt = 0; nt < 4; nt++) {
                    asm("mma.sync.aligned.m16n8k8.row.col.f32.tf32.tf32.f32 "
                        "{%0,%1,%2,%3},{%4,%5,%6,%7},{%8,%9},{%0,%1,%2,%3};"
                        : "+f"(acc[mt][nt][0]), "+f"(acc[mt][nt][1]),
                          "+f"(acc[mt][nt][2]), "+f"(acc[mt][nt][3])
                        : "r"(a[mt][0]), "r"(a[mt][1]), "r"(a[mt][2]), "r"(a[mt][3]),
                          "r"(b[nt][0]), "r"(b[nt][1]));
                }
        }
        __syncthreads();
    }

    // ---- epilogue
#pragma unroll
    for (int mt = 0; mt < 2; mt++) {
        int m = m0 + warpM*32 + mt*16 + r;
#pragma unroll
        for (int nt = 0; nt < 4; nt++) {
            int n = n0 + warpN*32 + nt*8 + 2*c;
            float2 bz = *reinterpret_cast<const float2*>(bias + n);
            float2 lo = make_float2(acc[mt][nt][0] + bz.x, acc[mt][nt][1] + bz.y);
            float2 hi = make_float2(acc[mt][nt][2] + bz.x, acc[mt][nt][3] + bz.y);
            *reinterpret_cast<float2*>(g_logits + (size_t)m * VOCAB + n)       = lo;
            *reinterpret_cast<float2*>(g_logits + (size_t)(m+8) * VOCAB + n)   = hi;
        }
    }
}

// ---------------------------------------------------------------------------
// Online log-softmax per row
// ---------------------------------------------------------------------------
__global__ __launch_bounds__(256) void kSoftmax(float* __restrict__ out) {
    const int r = blockIdx.x;
    const float* __restrict__ row = g_logits + (size_t)r * VOCAB;
    float m = -INFINITY, s = 0.f;
    for (int v = threadIdx.x; v < VOCAB; v += 256) {
        float x = row[v];
        if (x > m) { s = s * expf(m - x) + 1.f; m = x; }
        else       { s += expf(x - m); }
    }
    __shared__ float sm[256], ss[256];
    sm[threadIdx.x] = m; ss[threadIdx.x] = s;
    __syncthreads();
    for (int st = 128; st > 0; st >>= 1) {
        if (threadIdx.x < st) {
            float m2 = sm[threadIdx.x + st], s2 = ss[threadIdx.x + st];
            float m1 = sm[threadIdx.x],      s1 = ss[threadIdx.x];
            float M = fmaxf(m1, m2);
            sm[threadIdx.x] = M;
            ss[threadIdx.x] = s1 * expf(m1 - M) + s2 * expf(m2 - M);
        }
        __syncthreads();
    }
    const float lse = sm[0] + logf(ss[0]);
    float* __restrict__ orow = out + (size_t)r * VOCAB;
    for (int v = threadIdx.x; v < VOCAB; v += 256)
        orow[v] = row[v] - lse;
}

// ---------------------------------------------------------------------------
// Launch
// ---------------------------------------------------------------------------
extern "C" void kernel_launch(void* const* d_in, const int* in_sizes, int n_in,
                              void* d_out, int out_size) {
    const int*   ids  = (const int*)  d_in[0];   // [64,32]
    const float* h0   = (const float*)d_in[1];   // [1,32,512]
    const float* emb  = (const float*)d_in[2];   // [32000,512]
    const float* W0   = (const float*)d_in[3];   // [1024,1024]
    const float* Ws   = (const float*)d_in[4];   // [8,8,512,1024]
    const float* bias = (const float*)d_in[5];   // [32000]
    float* out = (float*)d_out;                  // [64,32,32000] ++ [1,32,512]

    cudaFuncSetAttribute(kStage, cudaFuncAttributeMaxDynamicSharedMemorySize, STG_SMEM);

    kEmbed<<<RROWS, 128>>>(ids, emb);
    kXpreGemm<<<dim3(NH2/64, RROWS/64), 256>>>(W0);

    const float* W0h = W0 + (size_t)NH * NH2;
    for (int t = 0; t < TSTEPS; t++) {
        kStage<<<dim3(32, 1), 128, STG_SMEM>>>(W0h, h0, -1, t);
        for (int i = 0; i < 7; i++)
            kStage<<<dim3(32, 7 - i), 128, STG_SMEM>>>(Ws, nullptr, i, t);
    }
    kAvgFinal<<<64, 256>>>(out + (size_t)RROWS * VOCAB);

    kDecMMA<<<dim3(VOCAB/64, RROWS/128), 256>>>(emb, bias);
    kSoftmax<<<RROWS, 256>>>(out);
}